// round 7
// baseline (speedup 1.0000x reference)
#include <cuda_runtime.h>
#include <math.h>
#include <stdint.h>

#define NMAXT 3329      // 1024 query + 1 sep + 2304 max prompts (logical)
#define NPAD  3344      // token-dim padding (multiple of 16)
#define SLD   3344      // score-matrix row stride
#define GPTS  2304
#define NBATCH 4

// converted-weight scratch layout (floats)
#define WOFF_QKV  0LL                    // 2 x 1024*3072
#define WOFF_PROJ 6291456LL              // 2 x 1024*1024
#define WOFF_M1   8388608LL              // 2 x 1024*4096
#define WOFF_M2   16777216LL             // 2 x 4096*1024
#define WOFF_W2   25165824LL             // 512*1024
#define WC_TOTAL  25690112LL

// GEMM geometry
#define BM 256
#define BN 128
#define ASTG 5120            // 256*20 floats per stage
#define BSTG 2560            // max(128*20, 16*136) floats per stage
#define STG  7680            // floats per stage
#define NSTAGE 4
#define SMEM_BYTES (NSTAGE*STG*4)

// ---------------- static device scratch (zero-initialized, never freed) ---------
__device__ int   g_M[NBATCH];
__device__ int   g_rows[NBATCH*GPTS];
__device__ int   g_cols[NBATCH*GPTS];
__device__ float g_X   [(size_t)NBATCH*NPAD*1024];
__device__ float g_Y   [(size_t)NBATCH*NPAD*1024];
__device__ float g_QKV [(size_t)NBATCH*NPAD*3072];   // pad rows stay 0 (V zeros)
__device__ float g_S   [(size_t)NBATCH*4*NPAD*SLD];  // pad cols stay 0
__device__ float g_Hbuf[(size_t)NBATCH*NPAD*4096];
__device__ float g_Qpe [1024*1024];
__device__ float g_Ppe [(size_t)NBATCH*GPTS*1024];
__device__ float g_Hp  [(size_t)NBATCH*GPTS*512];
__device__ float g_Pft [(size_t)NBATCH*GPTS*1024];
__device__ float g_Wc  [WC_TOTAL];

__device__ __forceinline__ float geluf(float x) {
    return 0.5f * x * (1.0f + erff(x * 0.7071067811865475f));
}
__device__ __forceinline__ float tf32r(float x) {
    float r; asm("cvt.rna.tf32.f32 %0, %1;" : "=f"(r) : "f"(x)); return r;
}
__device__ __forceinline__ float warpSum(float v) {
    #pragma unroll
    for (int o = 16; o; o >>= 1) v += __shfl_xor_sync(0xFFFFFFFFu, v, o);
    return v;
}
__device__ __forceinline__ float warpMax(float v) {
    #pragma unroll
    for (int o = 16; o; o >>= 1) v = fmaxf(v, __shfl_xor_sync(0xFFFFFFFFu, v, o));
    return v;
}

// ---------------- weight pre-round to tf32 (rna) --------------------------------
__global__ void wcvt_k(const float* __restrict__ src, float* __restrict__ dst, int n4) {
    int i = blockIdx.x * blockDim.x + threadIdx.x;
    if (i >= n4) return;
    float4 v = ((const float4*)src)[i];
    v.x = tf32r(v.x); v.y = tf32r(v.y); v.z = tf32r(v.z); v.w = tf32r(v.w);
    ((float4*)dst)[i] = v;
}

// ---------------- mask compaction (row-major order == np.nonzero) ---------------
__global__ void compact_k(const int* __restrict__ mask) {
    int b = threadIdx.x;
    if (b >= NBATCH) return;
    const int* mb = mask + b * GPTS;
    int cnt = 0;
    for (int i = 0; i < GPTS; i++) {
        if (mb[i] > 0) {
            g_rows[b*GPTS + cnt] = i / 48;
            g_cols[b*GPTS + cnt] = i % 48;
            cnt++;
        }
    }
    g_M[b] = cnt;
}

// ---------------- query positional encoding -------------------------------------
__global__ void qpe_k(const float* __restrict__ gauss) {
    int t = blockIdx.x;            // t = i*32 + j
    int i = t >> 5, j = t & 31;
    float cx = 2.0f * ((j + 0.5f) / 32.0f) - 1.0f;
    float cy = 2.0f * ((i + 0.5f) / 32.0f) - 1.0f;
    for (int k = threadIdx.x; k < 512; k += 256) {
        float ang = 6.283185307179586f * (cx * gauss[k] + cy * gauss[512 + k]);
        g_Qpe[(size_t)t*1024 + k]       = sinf(ang);
        g_Qpe[(size_t)t*1024 + 512 + k] = cosf(ang);
    }
}

// ------------- prompt PE + depth hidden layer gelu(d*w1+b1) ---------------------
__global__ void pembed_k(const float* __restrict__ depth, const float* __restrict__ gauss,
                         const float* __restrict__ w1, const float* __restrict__ b1) {
    int b = blockIdx.y, j = blockIdx.x;
    if (j >= g_M[b]) return;
    int r = g_rows[b*GPTS + j], c = g_cols[b*GPTS + j];
    float cx = 2.0f * ((c + 0.5f) / 48.0f) - 1.0f;
    float cy = 2.0f * ((r + 0.5f) / 48.0f) - 1.0f;
    float d = depth[b*GPTS + r*48 + c];
    size_t base = (size_t)b*GPTS + j;
    for (int k = threadIdx.x; k < 512; k += 256) {
        float ang = 6.283185307179586f * (cx * gauss[k] + cy * gauss[512 + k]);
        g_Ppe[base*1024 + k]       = sinf(ang);
        g_Ppe[base*1024 + 512 + k] = cosf(ang);
        g_Hp [base*512  + k]       = tf32r(geluf(fmaf(d, w1[k], b1[k])));  // GEMM input
    }
}

// ---------------- build residual stream -----------------------------------------
__global__ void build_x(const float* __restrict__ img, const float* __restrict__ sep0) {
    int b = blockIdx.y, t = blockIdx.x;
    if (t >= 1025 + g_M[b]) return;
    float* x = g_X + ((size_t)b*NPAD + t) * 1024;
    if (t < 1024) {
        const float* im = img + ((size_t)b*1024 + t) * 1024;
        for (int c = threadIdx.x; c < 1024; c += 256) x[c] = im[c] + g_Qpe[(size_t)t*1024 + c];
    } else if (t == 1024) {
        for (int c = threadIdx.x; c < 1024; c += 256) x[c] = sep0[c];
    } else {
        size_t base = (size_t)b*GPTS + (t - 1025);
        for (int c = threadIdx.x; c < 1024; c += 256)
            x[c] = g_Pft[base*1024 + c] + g_Ppe[base*1024 + c];
    }
}

__global__ void sep_rep(const float* __restrict__ sep1) {
    int b = blockIdx.x;
    float* x = g_X + ((size_t)b*NPAD + 1024) * 1024;
    for (int c = threadIdx.x; c < 1024; c += blockDim.x) x[c] = sep1[c];
}

// ---------------- layernorm (output is a GEMM input -> store rounded) -----------
__global__ void ln_k(const float* __restrict__ Xin, float* __restrict__ Yout,
                     const float* __restrict__ w, const float* __restrict__ bb) {
    int b = blockIdx.y, t = blockIdx.x;
    if (t >= 1025 + g_M[b]) return;
    int tid = threadIdx.x;
    const float4* x4 = (const float4*)(Xin + ((size_t)b*NPAD + t) * 1024);
    float4 v = x4[tid];
    float s  = v.x + v.y + v.z + v.w;
    float sq = v.x*v.x + v.y*v.y + v.z*v.z + v.w*v.w;
    __shared__ float shs[8], shq[8], res[2];
    float ws = warpSum(s), wq = warpSum(sq);
    if ((tid & 31) == 0) { shs[tid>>5] = ws; shq[tid>>5] = wq; }
    __syncthreads();
    if (tid == 0) {
        float a = 0.f, q = 0.f;
        #pragma unroll
        for (int i = 0; i < 8; i++) { a += shs[i]; q += shq[i]; }
        res[0] = a; res[1] = q;
    }
    __syncthreads();
    float mean = res[0] * (1.0f/1024.0f);
    float var  = res[1] * (1.0f/1024.0f) - mean*mean;
    float rstd = rsqrtf(var + 1e-5f);
    float4 wv = ((const float4*)w)[tid];
    float4 bv = ((const float4*)bb)[tid];
    float4 o;
    o.x = tf32r((v.x - mean) * rstd * wv.x + bv.x);
    o.y = tf32r((v.y - mean) * rstd * wv.y + bv.y);
    o.z = tf32r((v.z - mean) * rstd * wv.z + bv.z);
    o.w = tf32r((v.w - mean) * rstd * wv.w + bv.w);
    ((float4*)(Yout + ((size_t)b*NPAD + t) * 1024))[tid] = o;
}

// ---------------- fused single-pass row softmax (store rounded) -----------------
__global__ void softmax_k() {
    int z = blockIdx.y;            // b*4 + head
    int b = z >> 2;
    int Nd = 1025 + g_M[b];
    int row = blockIdx.x;
    if (row >= Nd) return;
    float* s = g_S + (size_t)z*NPAD*SLD + (size_t)row*SLD;
    int tid = threadIdx.x;
    __shared__ float red[8];

    float vals[14];
    float m = -3.4e38f;
    #pragma unroll
    for (int t = 0; t < 14; t++) {
        int j = tid + t*256;
        if (j < Nd) { vals[t] = s[j]; m = fmaxf(m, vals[t]); }
    }
    m = warpMax(m);
    if ((tid & 31) == 0) red[tid>>5] = m;
    __syncthreads();
    if (tid == 0) {
        float v = red[0];
        #pragma unroll
        for (int i = 1; i < 8; i++) v = fmaxf(v, red[i]);
        red[0] = v;
    }
    __syncthreads();
    m = red[0];
    __syncthreads();

    float sum = 0.f;
    #pragma unroll
    for (int t = 0; t < 14; t++) {
        int j = tid + t*256;
        if (j < Nd) { vals[t] = expf(vals[t] - m); sum += vals[t]; }
    }
    sum = warpSum(sum);
    if ((tid & 31) == 0) red[tid>>5] = sum;
    __syncthreads();
    if (tid == 0) {
        float v = 0.f;
        #pragma unroll
        for (int i = 0; i < 8; i++) v += red[i];
        red[0] = v;
    }
    __syncthreads();
    float inv = 1.0f / red[0];
    #pragma unroll
    for (int t = 0; t < 14; t++) {
        int j = tid + t*256;
        if (j < Nd) s[j] = tf32r(vals[t] * inv);
    }
}

// =========================== tf32 tensor-core GEMM ==============================
// C = alpha * A @ (TRANSB ? B^T : B) (+bias)(+gelu)(+=C)(ROUNDC: tf32-round store)
// All GEMM inputs pre-rounded to tf32 -> pure LDS+MMA mainloop.
// 256x128 CTA tile, 8 warps (4x2), 64x64 warp tile, m16n8k8 tf32 mma,
// 4-stage cp.async ring, ONE __syncthreads per k-tile.
__device__ __forceinline__ int dimval(int st, int dyn, int b) {
    if (dyn == 1) return 1025 + g_M[b];
    if (dyn == 2) return g_M[b];
    return st;
}

__device__ __forceinline__ void cpa16(uint32_t dst, const void* src, int srcBytes) {
    asm volatile("cp.async.cg.shared.global [%0], [%1], 16, %2;"
                 :: "r"(dst), "l"(src), "r"(srcBytes));
}

#define MMA_TF32(d, a, bq)                                              \
    asm volatile("mma.sync.aligned.m16n8k8.row.col.f32.tf32.tf32.f32 "  \
        "{%0,%1,%2,%3},{%4,%5,%6,%7},{%8,%9},{%0,%1,%2,%3};"            \
        : "+f"(d[0]),"+f"(d[1]),"+f"(d[2]),"+f"(d[3])                   \
        : "r"(a[0]),"r"(a[1]),"r"(a[2]),"r"(a[3]),"r"(bq[0]),"r"(bq[1]))

template<bool TRANSB, int EPI, bool ACCUM, bool ROUNDC>
__global__ void __launch_bounds__(256, 1) gemm_tc(
    const float* __restrict__ A, long long aOut, long long aIn, int lda,
    const float* __restrict__ B, long long bOut, long long bIn, int ldb,
    float* __restrict__ C, long long cOut, long long cIn, int ldc,
    const float* __restrict__ bias,
    int nInner, int Mst, int Nst, int Kst,
    int dynM, int dynN, int dynK, float alpha)
{
    int z = blockIdx.z;
    int b = z / nInner, ii = z - b*nInner;
    int Mr = dimval(Mst, dynM, b);
    int Nc = dimval(Nst, dynN, b);
    int K  = dimval(Kst, dynK, b);
    int Kpad = (K + 15) & ~15;          // padding regions hold zeros by construction
    int m0 = blockIdx.y * BM, n0 = blockIdx.x * BN;
    if (m0 >= Mr || n0 >= Nc) return;
    A += b*aOut + ii*aIn;
    B += b*bOut + ii*bIn;
    C += b*cOut + ii*cIn;

    extern __shared__ __align__(16) float smem[];
    uint32_t sbase = (uint32_t)__cvta_generic_to_shared(smem);

    int tid  = threadIdx.x;
    int wid  = tid >> 5, lane = tid & 31;
    int wm   = (wid >> 1) * 64;         // 4 warps along M
    int wn   = (wid & 1) * 64;          // 2 warps along N
    int g    = lane >> 2, t4 = lane & 3;

    float acc[4][8][4];
    #pragma unroll
    for (int i = 0; i < 4; i++)
        #pragma unroll
        for (int j = 0; j < 8; j++)
            #pragma unroll
            for (int e = 0; e < 4; e++) acc[i][j][e] = 0.f;

    auto issue = [&](int kt, int stg) {
        int k0 = kt << 4;
        uint32_t sA = sbase + (uint32_t)(stg*STG)*4;
        uint32_t sB = sA + (uint32_t)ASTG*4;
        // A tile: 256x16 -> 1024 float4, 4 per thread
        #pragma unroll
        for (int i = 0; i < 4; i++) {
            int idx = tid + 256*i;
            int r = idx >> 2, c4 = (idx & 3) << 2;
            int gm = m0 + r;
            bool ok = gm < Mr;
            const float* src = ok ? (A + (long long)gm*lda + k0 + c4) : A;
            cpa16(sA + (uint32_t)(r*20 + c4)*4, src, ok ? 16 : 0);
        }
        if (TRANSB) {
            // B tile [n(128)][k(16)] stride 20 -> 512 float4, 2 per thread
            #pragma unroll
            for (int i = 0; i < 2; i++) {
                int idx = tid + 256*i;
                int r = idx >> 2, c4 = (idx & 3) << 2;    // r = n, c4 = k
                int gn = n0 + r;
                bool ok = gn < Nc;
                const float* src = ok ? (B + (long long)gn*ldb + k0 + c4) : B;
                cpa16(sB + (uint32_t)(r*20 + c4)*4, src, ok ? 16 : 0);
            }
        } else {
            // B tile [k(16)][n(128)] stride 136; N static mult of 128, K rows in-alloc
            #pragma unroll
            for (int i = 0; i < 2; i++) {
                int idx = tid + 256*i;
                int r = idx >> 5, c4 = (idx & 31) << 2;   // r = k, c4 = n
                const float* src = B + (long long)(k0 + r)*ldb + n0 + c4;
                cpa16(sB + (uint32_t)(r*136 + c4)*4, src, 16);
            }
        }
    };

    auto compute = [&](int stg) {
        const float* Ab = smem + stg*STG;
        const float* Bb = Ab + ASTG;
        #pragma unroll
        for (int ks = 0; ks < 2; ks++) {
            int kk = ks * 8;
            uint32_t af[4][4], bf[8][2];
            #pragma unroll
            for (int mf = 0; mf < 4; mf++) {
                int r = wm + mf*16;
                af[mf][0] = __float_as_uint(Ab[(r+g  )*20 + kk+t4  ]);
                af[mf][1] = __float_as_uint(Ab[(r+g+8)*20 + kk+t4  ]);
                af[mf][2] = __float_as_uint(Ab[(r+g  )*20 + kk+t4+4]);
                af[mf][3] = __float_as_uint(Ab[(r+g+8)*20 + kk+t4+4]);
            }
            #pragma unroll
            for (int nf = 0; nf < 8; nf++) {
                int c = wn + nf*8 + g;
                if (TRANSB) {
                    bf[nf][0] = __float_as_uint(Bb[c*20 + kk+t4  ]);
                    bf[nf][1] = __float_as_uint(Bb[c*20 + kk+t4+4]);
                } else {
                    bf[nf][0] = __float_as_uint(Bb[(kk+t4  )*136 + c]);
                    bf[nf][1] = __float_as_uint(Bb[(kk+t4+4)*136 + c]);
                }
            }
            #pragma unroll
            for (int mf = 0; mf < 4; mf++)
                #pragma unroll
                for (int nf = 0; nf < 8; nf++)
                    MMA_TF32(acc[mf][nf], af[mf], bf[nf]);
        }
    };

    int ntiles = Kpad >> 4;
    // prologue: fill 3 of 4 stages
    #pragma unroll
    for (int p = 0; p < NSTAGE - 1; p++) {
        if (p < ntiles) issue(p, p);
        asm volatile("cp.async.commit_group;" ::: "memory");
    }
    for (int it = 0; it < ntiles; it++) {
        asm volatile("cp.async.wait_group %0;" :: "n"(NSTAGE - 2) : "memory");
        __syncthreads();
        if (it + NSTAGE - 1 < ntiles) issue(it + NSTAGE - 1, (it + NSTAGE - 1) & (NSTAGE - 1));
        asm volatile("cp.async.commit_group;" ::: "memory");
        compute(it & (NSTAGE - 1));
    }

    // ---- epilogue ----
    #pragma unroll
    for (int mf = 0; mf < 4; mf++) {
        #pragma unroll
        for (int nf = 0; nf < 8; nf++) {
            int gmA = m0 + wm + mf*16 + g;
            int gnA = n0 + wn + nf*8 + 2*t4;
            #pragma unroll
            for (int e = 0; e < 4; e++) {
                int gm = gmA + ((e >> 1) << 3);
                int gn = gnA + (e & 1);
                if (gm < Mr && gn < Nc) {
                    float v = acc[mf][nf][e] * alpha;
                    if (bias) v += bias[gn];
                    if (EPI == 1) v = geluf(v);
                    if (ROUNDC) v = tf32r(v);
                    long long off = (long long)gm*ldc + gn;
                    if (ACCUM) C[off] += v;
                    else       C[off]  = v;
                }
            }
        }
    }
}

// ---------------- output ---------------------------------------------------------
__global__ void out_k(const float* __restrict__ img, float* __restrict__ out) {
    int b = blockIdx.y, t = blockIdx.x;
    const float* src = (g_M[b] == 0)
        ? img + ((size_t)b*1024 + t) * 1024
        : g_X + ((size_t)b*NPAD + t) * 1024;
    float* o = out + ((size_t)b*1024 + t) * 1024;
    for (int c = threadIdx.x; c < 1024; c += 256) o[c] = src[c];
}

// ================================ host ==========================================
extern "C" void kernel_launch(void* const* d_in, const int* in_sizes, int n_in,
                              void* d_out, int out_size) {
    const float* img   = (const float*)d_in[0];
    const float* depth = (const float*)d_in[1];
    const int*   mask  = (const int*)  d_in[2];
    const float* gauss = (const float*)d_in[5];
    const float* w1    = (const float*)d_in[6];
    const float* b1    = (const float*)d_in[7];
    const float* w2    = (const float*)d_in[8];
    const float* b2    = (const float*)d_in[9];
    const float* sep   = (const float*)d_in[10];
    const float* ln1w  = (const float*)d_in[11];
    const float* ln1b  = (const float*)d_in[12];
    const float* qkvw  = (const float*)d_in[13];
    const float* qkvb  = (const float*)d_in[14];
    const float* projw = (const float*)d_in[15];
    const float* projb = (const float*)d_in[16];
    const float* ln2w  = (const float*)d_in[17];
    const float* ln2b  = (const float*)d_in[18];
    const float* m1w   = (const float*)d_in[19];
    const float* m1b   = (const float*)d_in[20];
    const float* m2w   = (const float*)d_in[21];
    const float* m2b   = (const float*)d_in[22];
    float* out = (float*)d_out;

    // allow 120KB dynamic smem on all instantiations (idempotent, non-stream call)
    cudaFuncSetAttribute(gemm_tc<false,0,false,false>, cudaFuncAttributeMaxDynamicSharedMemorySize, SMEM_BYTES);
    cudaFuncSetAttribute(gemm_tc<false,0,false,true >, cudaFuncAttributeMaxDynamicSharedMemorySize, SMEM_BYTES);
    cudaFuncSetAttribute(gemm_tc<true ,0,false,false>, cudaFuncAttributeMaxDynamicSharedMemorySize, SMEM_BYTES);
    cudaFuncSetAttribute(gemm_tc<false,0,true ,false>, cudaFuncAttributeMaxDynamicSharedMemorySize, SMEM_BYTES);
    cudaFuncSetAttribute(gemm_tc<false,1,false,true >, cudaFuncAttributeMaxDynamicSharedMemorySize, SMEM_BYTES);

    float *pX, *pY, *pQKV, *pS, *pH, *pHp, *pPft, *pWc;
    cudaGetSymbolAddress((void**)&pX,   g_X);
    cudaGetSymbolAddress((void**)&pY,   g_Y);
    cudaGetSymbolAddress((void**)&pQKV, g_QKV);
    cudaGetSymbolAddress((void**)&pS,   g_S);
    cudaGetSymbolAddress((void**)&pH,   g_Hbuf);
    cudaGetSymbolAddress((void**)&pHp,  g_Hp);
    cudaGetSymbolAddress((void**)&pPft, g_Pft);
    cudaGetSymbolAddress((void**)&pWc,  g_Wc);

    const long long SX   = (long long)NPAD * 1024;
    const long long SQKV = (long long)NPAD * 3072;
    const long long SH   = (long long)NPAD * 4096;
    const long long SS1  = (long long)NPAD * SLD;    // per head
    const long long SSB  = 4LL * SS1;                // per batch

    // --- pre-round all GEMM weights to tf32 (rna) once per call ---
    {
        auto cvt = [&](const float* src, long long dstOff, long long n) {
            int n4 = (int)(n >> 2);
            wcvt_k<<<(n4 + 255)/256, 256>>>(src, pWc + dstOff, n4);
        };
        cvt(qkvw, WOFF_QKV, 2LL*1024*3072);
        cvt(projw, WOFF_PROJ, 2LL*1024*1024);
        cvt(m1w, WOFF_M1, 2LL*1024*4096);
        cvt(m2w, WOFF_M2, 2LL*4096*1024);
        cvt(w2, WOFF_W2, 512LL*1024);
    }
    const float* qkvwC  = pWc + WOFF_QKV;
    const float* projwC = pWc + WOFF_PROJ;
    const float* m1wC   = pWc + WOFF_M1;
    const float* m2wC   = pWc + WOFF_M2;
    const float* w2C    = pWc + WOFF_W2;

    compact_k<<<1, NBATCH>>>(mask);
    qpe_k<<<1024, 256>>>(gauss);
    pembed_k<<<dim3(GPTS, NBATCH), 256>>>(depth, gauss, w1, b1);

    // prompt features: Pft = Hp @ w2 + b2   (rows = g_M[b]); feeds X only -> no round
    gemm_tc<false,0,false,false><<<dim3(8, 9, NBATCH), 256, SMEM_BYTES>>>(
        pHp, (long long)GPTS*512, 0, 512,
        w2C, 0, 0, 1024,
        pPft, (long long)GPTS*1024, 0, 1024,
        b2, 1, 0, 1024, 512, 2, 0, 0, 1.0f);

    build_x<<<dim3(NMAXT, NBATCH), 256>>>(img, sep);

    for (int i = 0; i < 2; i++) {
        if (i) sep_rep<<<NBATCH, 256>>>(sep + (size_t)i*1024);

        ln_k<<<dim3(NMAXT, NBATCH), 256>>>(pX, pY, ln1w + i*1024, ln1b + i*1024);

        // QKV = Y @ qkv_w + qkv_b  (feeds QK^T and S@V -> rounded store)
        gemm_tc<false,0,false,true><<<dim3(24, 14, NBATCH), 256, SMEM_BYTES>>>(
            pY, SX, 0, 1024,
            qkvwC + (size_t)i*1024*3072, 0, 0, 3072,
            pQKV, SQKV, 0, 3072,
            qkvb + (size_t)i*3072, 1, 0, 3072, 1024, 1, 0, 0, 1.0f);

        // S = Q K^T / 16  (feeds softmax, which re-rounds -> no round here)
        gemm_tc<true,0,false,false><<<dim3(27, 14, NBATCH*4), 256, SMEM_BYTES>>>(
            pQKV, SQKV, 256, 3072,
            pQKV + 1024, SQKV, 256, 3072,
            pS, SSB, SS1, SLD,
            nullptr, 4, 0, 0, 256, 1, 1, 0, 0.0625f);

        softmax_k<<<dim3(NMAXT, NBATCH*4), 256>>>();

        // O = S @ V -> Y (feeds proj GEMM -> rounded store)
        gemm_tc<false,0,false,true><<<dim3(2, 14, NBATCH*4), 256, SMEM_BYTES>>>(
            pS, SSB, SS1, SLD,
            pQKV + 2048, SQKV, 256, 3072,
            pY, SX, 256, 1024,
            nullptr, 4, 0, 256, 0, 1, 0, 1, 1.0f);

        // X += O @ proj_w + proj_b  (residual stays fp32)
        gemm_tc<false,0,true,false><<<dim3(8, 14, NBATCH), 256, SMEM_BYTES>>>(
            pY, SX, 0, 1024,
            projwC + (size_t)i*1024*1024, 0, 0, 1024,
            pX, SX, 0, 1024,
            projb + (size_t)i*1024, 1, 0, 1024, 1024, 1, 0, 0, 1.0f);

        ln_k<<<dim3(NMAXT, NBATCH), 256>>>(pX, pY, ln2w + i*1024, ln2b + i*1024);

        // H = gelu(Y @ mlp_w1 + mlp_b1)  (feeds MLP2 -> rounded store)
        gemm_tc<false,1,false,true><<<dim3(32, 14, NBATCH), 256, SMEM_BYTES>>>(
            pY, SX, 0, 1024,
            m1wC + (size_t)i*1024*4096, 0, 0, 4096,
            pH, SH, 0, 4096,
            m1b + (size_t)i*4096, 1, 0, 4096, 1024, 1, 0, 0, 1.0f);

        // X += H @ mlp_w2 + mlp_b2  (residual stays fp32)
        gemm_tc<false,0,true,false><<<dim3(8, 14, NBATCH), 256, SMEM_BYTES>>>(
            pH, SH, 0, 4096,
            m2wC + (size_t)i*4096*1024, 0, 0, 1024,
            pX, SX, 0, 1024,
            m2b + (size_t)i*1024, 1, 0, 1024, 4096, 1, 0, 0, 1.0f);
    }

    out_k<<<dim3(1024, NBATCH), 256>>>(img, out);
}

// round 8
// speedup vs baseline: 1.8529x; 1.8529x over previous
#include <cuda_runtime.h>
#include <cuda_fp16.h>
#include <math.h>
#include <stdint.h>

#define NMAXT 3329      // 1024 query + 1 sep + 2304 max prompts (logical)
#define NPAD  3344      // token-dim padding (multiple of 16, mult of 8 for cp.async)
#define SLD   3344      // score-matrix row stride
#define GPTS  2304
#define NBATCH 4

// transposed-half-weight scratch layout (element offsets)
#define WOFF_QKV  0LL                    // 2 x [3072][1024]
#define WOFF_PROJ 6291456LL              // 2 x [1024][1024]
#define WOFF_M1   8388608LL              // 2 x [4096][1024]
#define WOFF_M2   16777216LL             // 2 x [1024][4096]
#define WOFF_W2   25165824LL             // [1024][512]
#define WC_TOTAL  25690112LL

// ---------------- static device scratch (zero-initialized, never freed) ---------
__device__ int    g_M[NBATCH];
__device__ int    g_rows[NBATCH*GPTS];
__device__ int    g_cols[NBATCH*GPTS];
__device__ float  g_X   [(size_t)NBATCH*NPAD*1024];            // residual, fp32
__device__ __half g_Yh  [(size_t)NBATCH*NPAD*1024];            // LN out / attn out
__device__ __half g_QKVh[(size_t)NBATCH*NPAD*3072];            // pad rows stay 0
__device__ float  g_S   [(size_t)NBATCH*4*NPAD*SLD];           // logits fp32
__device__ __half g_Sh  [(size_t)NBATCH*4*NPAD*SLD];           // probs half, pad 0
__device__ __half g_Hh  [(size_t)NBATCH*NPAD*4096];            // MLP hidden
__device__ __half g_Vt  [(size_t)NBATCH*1024*NPAD];            // V transposed [dim][tok]
__device__ float  g_Qpe [1024*1024];
__device__ float  g_Ppe [(size_t)NBATCH*GPTS*1024];
__device__ __half g_Hph [(size_t)NBATCH*GPTS*512];
__device__ float  g_Pft [(size_t)NBATCH*GPTS*1024];
__device__ __half g_Wch [WC_TOTAL];

__device__ __forceinline__ float geluf(float x) {
    return 0.5f * x * (1.0f + erff(x * 0.7071067811865475f));
}
__device__ __forceinline__ float warpSum(float v) {
    #pragma unroll
    for (int o = 16; o; o >>= 1) v += __shfl_xor_sync(0xFFFFFFFFu, v, o);
    return v;
}
__device__ __forceinline__ float warpMax(float v) {
    #pragma unroll
    for (int o = 16; o; o >>= 1) v = fmaxf(v, __shfl_xor_sync(0xFFFFFFFFu, v, o));
    return v;
}

// ---------------- weight transpose fp32[K][N] -> half[N][K] ---------------------
__global__ void wtr_k(const float* __restrict__ src, __half* __restrict__ dst,
                      int K, int N) {
    __shared__ float t[32][33];
    src += (size_t)blockIdx.z * K * N;
    dst += (size_t)blockIdx.z * K * N;
    int n0 = blockIdx.x * 32, k0 = blockIdx.y * 32;
    int tx = threadIdx.x, ty = threadIdx.y;
    #pragma unroll
    for (int i = 0; i < 32; i += 8)
        t[ty + i][tx] = src[(size_t)(k0 + ty + i) * N + n0 + tx];
    __syncthreads();
    #pragma unroll
    for (int i = 0; i < 32; i += 8)
        dst[(size_t)(n0 + ty + i) * K + k0 + tx] = __float2half_rn(t[tx][ty + i]);
}

// ---------------- V transpose half [tok][dim] -> half [dim][tok] ----------------
__global__ void vtr_k(const __half* __restrict__ QKVh, __half* __restrict__ Vt) {
    __shared__ __half t[32][40];
    int b = blockIdx.z;
    const __half* src = QKVh + (size_t)b*NPAD*3072 + 2048;
    __half* dst = Vt + (size_t)b*1024*NPAD;
    int t0 = blockIdx.x * 32, n0 = blockIdx.y * 32;
    int tx = threadIdx.x, ty = threadIdx.y;
    #pragma unroll
    for (int i = 0; i < 32; i += 8) {
        int tt = t0 + ty + i;
        t[ty + i][tx] = (tt < NPAD) ? src[(size_t)tt*3072 + n0 + tx] : __half(0.f);
    }
    __syncthreads();
    #pragma unroll
    for (int i = 0; i < 32; i += 8) {
        int tt = t0 + tx;
        if (tt < NPAD) dst[(size_t)(n0 + ty + i)*NPAD + tt] = t[tx][ty + i];
    }
}

// ---------------- mask compaction (row-major order == np.nonzero) ---------------
__global__ void compact_k(const int* __restrict__ mask) {
    int b = threadIdx.x;
    if (b >= NBATCH) return;
    const int* mb = mask + b * GPTS;
    int cnt = 0;
    for (int i = 0; i < GPTS; i++) {
        if (mb[i] > 0) {
            g_rows[b*GPTS + cnt] = i / 48;
            g_cols[b*GPTS + cnt] = i % 48;
            cnt++;
        }
    }
    g_M[b] = cnt;
}

// ---------------- query positional encoding -------------------------------------
__global__ void qpe_k(const float* __restrict__ gauss) {
    int t = blockIdx.x;            // t = i*32 + j
    int i = t >> 5, j = t & 31;
    float cx = 2.0f * ((j + 0.5f) / 32.0f) - 1.0f;
    float cy = 2.0f * ((i + 0.5f) / 32.0f) - 1.0f;
    for (int k = threadIdx.x; k < 512; k += 256) {
        float ang = 6.283185307179586f * (cx * gauss[k] + cy * gauss[512 + k]);
        g_Qpe[(size_t)t*1024 + k]       = sinf(ang);
        g_Qpe[(size_t)t*1024 + 512 + k] = cosf(ang);
    }
}

// ------------- prompt PE + depth hidden layer gelu(d*w1+b1) ---------------------
__global__ void pembed_k(const float* __restrict__ depth, const float* __restrict__ gauss,
                         const float* __restrict__ w1, const float* __restrict__ b1) {
    int b = blockIdx.y, j = blockIdx.x;
    if (j >= g_M[b]) return;
    int r = g_rows[b*GPTS + j], c = g_cols[b*GPTS + j];
    float cx = 2.0f * ((c + 0.5f) / 48.0f) - 1.0f;
    float cy = 2.0f * ((r + 0.5f) / 48.0f) - 1.0f;
    float d = depth[b*GPTS + r*48 + c];
    size_t base = (size_t)b*GPTS + j;
    for (int k = threadIdx.x; k < 512; k += 256) {
        float ang = 6.283185307179586f * (cx * gauss[k] + cy * gauss[512 + k]);
        g_Ppe[base*1024 + k]       = sinf(ang);
        g_Ppe[base*1024 + 512 + k] = cosf(ang);
        g_Hph[base*512  + k]       = __float2half_rn(geluf(fmaf(d, w1[k], b1[k])));
    }
}

// ---------------- build residual stream -----------------------------------------
__global__ void build_x(const float* __restrict__ img, const float* __restrict__ sep0) {
    int b = blockIdx.y, t = blockIdx.x;
    if (t >= 1025 + g_M[b]) return;
    float* x = g_X + ((size_t)b*NPAD + t) * 1024;
    if (t < 1024) {
        const float* im = img + ((size_t)b*1024 + t) * 1024;
        for (int c = threadIdx.x; c < 1024; c += 256) x[c] = im[c] + g_Qpe[(size_t)t*1024 + c];
    } else if (t == 1024) {
        for (int c = threadIdx.x; c < 1024; c += 256) x[c] = sep0[c];
    } else {
        size_t base = (size_t)b*GPTS + (t - 1025);
        for (int c = threadIdx.x; c < 1024; c += 256)
            x[c] = g_Pft[base*1024 + c] + g_Ppe[base*1024 + c];
    }
}

__global__ void sep_rep(const float* __restrict__ sep1) {
    int b = blockIdx.x;
    float* x = g_X + ((size_t)b*NPAD + 1024) * 1024;
    for (int c = threadIdx.x; c < 1024; c += blockDim.x) x[c] = sep1[c];
}

// ---------------- layernorm: fp32 in -> half out --------------------------------
__global__ void ln_k(const float* __restrict__ Xin, __half* __restrict__ Yout,
                     const float* __restrict__ w, const float* __restrict__ bb) {
    int b = blockIdx.y, t = blockIdx.x;
    if (t >= 1025 + g_M[b]) return;
    int tid = threadIdx.x;
    const float4* x4 = (const float4*)(Xin + ((size_t)b*NPAD + t) * 1024);
    float4 v = x4[tid];
    float s  = v.x + v.y + v.z + v.w;
    float sq = v.x*v.x + v.y*v.y + v.z*v.z + v.w*v.w;
    __shared__ float shs[8], shq[8], res[2];
    float ws = warpSum(s), wq = warpSum(sq);
    if ((tid & 31) == 0) { shs[tid>>5] = ws; shq[tid>>5] = wq; }
    __syncthreads();
    if (tid == 0) {
        float a = 0.f, q = 0.f;
        #pragma unroll
        for (int i = 0; i < 8; i++) { a += shs[i]; q += shq[i]; }
        res[0] = a; res[1] = q;
    }
    __syncthreads();
    float mean = res[0] * (1.0f/1024.0f);
    float var  = res[1] * (1.0f/1024.0f) - mean*mean;
    float rstd = rsqrtf(var + 1e-5f);
    float4 wv = ((const float4*)w)[tid];
    float4 bv = ((const float4*)bb)[tid];
    __half2* yrow = (__half2*)(Yout + ((size_t)b*NPAD + t) * 1024);
    yrow[2*tid]   = __floats2half2_rn((v.x - mean)*rstd*wv.x + bv.x,
                                      (v.y - mean)*rstd*wv.y + bv.y);
    yrow[2*tid+1] = __floats2half2_rn((v.z - mean)*rstd*wv.z + bv.z,
                                      (v.w - mean)*rstd*wv.w + bv.w);
}

// ---------------- row softmax: fp32 logits -> half probs ------------------------
__global__ void softmax_k() {
    int z = blockIdx.y;            // b*4 + head
    int b = z >> 2;
    int Nd = 1025 + g_M[b];
    int row = blockIdx.x;
    if (row >= Nd) return;
    const float* s = g_S  + (size_t)z*NPAD*SLD + (size_t)row*SLD;
    __half*     sh = g_Sh + (size_t)z*NPAD*SLD + (size_t)row*SLD;
    int tid = threadIdx.x;
    __shared__ float red[8];

    float vals[14];
    float m = -3.4e38f;
    #pragma unroll
    for (int t = 0; t < 14; t++) {
        int j = tid + t*256;
        if (j < Nd) { vals[t] = s[j]; m = fmaxf(m, vals[t]); }
    }
    m = warpMax(m);
    if ((tid & 31) == 0) red[tid>>5] = m;
    __syncthreads();
    if (tid == 0) {
        float v = red[0];
        #pragma unroll
        for (int i = 1; i < 8; i++) v = fmaxf(v, red[i]);
        red[0] = v;
    }
    __syncthreads();
    m = red[0];
    __syncthreads();

    float sum = 0.f;
    #pragma unroll
    for (int t = 0; t < 14; t++) {
        int j = tid + t*256;
        if (j < Nd) { vals[t] = expf(vals[t] - m); sum += vals[t]; }
    }
    sum = warpSum(sum);
    if ((tid & 31) == 0) red[tid>>5] = sum;
    __syncthreads();
    if (tid == 0) {
        float v = 0.f;
        #pragma unroll
        for (int i = 0; i < 8; i++) v += red[i];
        red[0] = v;
    }
    __syncthreads();
    float inv = 1.0f / red[0];
    #pragma unroll
    for (int t = 0; t < 14; t++) {
        int j = tid + t*256;
        if (j < Nd) sh[j] = __float2half_rn(vals[t] * inv);
    }
}

// =========================== fp16 tensor-core GEMM ==============================
// C = alpha * A @ B^T (+bias)(+gelu)(+=C fp32)(OUTH: half store)
// A: half [M][K] row-major; B: half [N][K] row-major (all operands n-major).
// 128x128x32 CTA tile, 8 warps (2x4), 64x32 warp tile, m16n8k16 f16 mma,
// 2-stage cp.async double buffer (proven R5 loop structure).
__device__ __forceinline__ int dimval(int st, int dyn, int b) {
    if (dyn == 1) return 1025 + g_M[b];
    if (dyn == 2) return g_M[b];
    return st;
}

__device__ __forceinline__ void cpa16(uint32_t dst, const void* src, int srcBytes) {
    asm volatile("cp.async.cg.shared.global [%0], [%1], 16, %2;"
                 :: "r"(dst), "l"(src), "r"(srcBytes));
}

#define MMA_F16(d, a, bq)                                                \
    asm volatile("mma.sync.aligned.m16n8k16.row.col.f32.f16.f16.f32 "    \
        "{%0,%1,%2,%3},{%4,%5,%6,%7},{%8,%9},{%0,%1,%2,%3};"             \
        : "+f"(d[0]),"+f"(d[1]),"+f"(d[2]),"+f"(d[3])                    \
        : "r"(a[0]),"r"(a[1]),"r"(a[2]),"r"(a[3]),"r"(bq[0]),"r"(bq[1]))

template<int EPI, bool ACCUM, bool OUTH>
__global__ void __launch_bounds__(256, 2) gemm_h(
    const __half* __restrict__ A, long long aOut, long long aIn, int lda,
    const __half* __restrict__ B, long long bOut, long long bIn, int ldb,
    void* __restrict__ Cv, long long cOut, long long cIn, int ldc,
    const float* __restrict__ bias,
    int nInner, int Mst, int Nst, int Kst,
    int dynM, int dynN, int dynK, float alpha)
{
    int z = blockIdx.z;
    int b = z / nInner, ii = z - b*nInner;
    int Mr = dimval(Mst, dynM, b);
    int Nc = dimval(Nst, dynN, b);
    int K  = dimval(Kst, dynK, b);
    int Kpad = (K + 31) & ~31;          // pad regions hold zeros by construction
    int m0 = blockIdx.y * 128, n0 = blockIdx.x * 128;
    if (m0 >= Mr || n0 >= Nc) return;
    A += b*aOut + ii*aIn;
    B += b*bOut + ii*bIn;

    // per stage: 128 rows x 16 words (32 halves) + 4 pad words -> 128*20 = 2560 u32
    __shared__ __align__(16) uint32_t Asm[2*2560];
    __shared__ __align__(16) uint32_t Bsm[2*2560];
    uint32_t sA = (uint32_t)__cvta_generic_to_shared(Asm);
    uint32_t sB = (uint32_t)__cvta_generic_to_shared(Bsm);

    int tid  = threadIdx.x;
    int wid  = tid >> 5, lane = tid & 31;
    int wm   = (wid >> 2) * 64;
    int wn   = (wid & 3) * 32;
    int g    = lane >> 2, t4 = lane & 3;

    float acc[4][4][4];
    #pragma unroll
    for (int i = 0; i < 4; i++)
        #pragma unroll
        for (int j = 0; j < 4; j++)
            #pragma unroll
            for (int e = 0; e < 4; e++) acc[i][j][e] = 0.f;

    auto issue = [&](int kt, int buf) {
        int k0 = kt << 5;                       // halves
        #pragma unroll
        for (int i = 0; i < 2; i++) {
            int idx = tid + 256*i;
            int r = idx >> 2, cw = (idx & 3) << 2;   // cw: word offset in row
            int gm = m0 + r;
            bool ok = gm < Mr;
            const __half* src = ok ? (A + (long long)gm*lda + k0 + (cw<<1)) : A;
            cpa16(sA + (uint32_t)(buf*2560 + r*20 + cw)*4, src, ok ? 16 : 0);
        }
        #pragma unroll
        for (int i = 0; i < 2; i++) {
            int idx = tid + 256*i;
            int r = idx >> 2, cw = (idx & 3) << 2;
            int gn = n0 + r;
            bool ok = gn < Nc;
            const __half* src = ok ? (B + (long long)gn*ldb + k0 + (cw<<1)) : B;
            cpa16(sB + (uint32_t)(buf*2560 + r*20 + cw)*4, src, ok ? 16 : 0);
        }
    };

    auto compute = [&](int buf) {
        const uint32_t* Ab = Asm + buf*2560;
        const uint32_t* Bb = Bsm + buf*2560;
        #pragma unroll
        for (int ks = 0; ks < 2; ks++) {
            int kw = ks << 3;                   // word offset of this k16 step
            uint32_t af[4][4], bf[4][2];
            #pragma unroll
            for (int mf = 0; mf < 4; mf++) {
                int r = wm + mf*16;
                af[mf][0] = Ab[(r+g  )*20 + kw + t4    ];
                af[mf][1] = Ab[(r+g+8)*20 + kw + t4    ];
                af[mf][2] = Ab[(r+g  )*20 + kw + t4 + 4];
                af[mf][3] = Ab[(r+g+8)*20 + kw + t4 + 4];
            }
            #pragma unroll
            for (int nf = 0; nf < 4; nf++) {
                int c = wn + nf*8 + g;
                bf[nf][0] = Bb[c*20 + kw + t4    ];
                bf[nf][1] = Bb[c*20 + kw + t4 + 4];
            }
            #pragma unroll
            for (int mf = 0; mf < 4; mf++)
                #pragma unroll
                for (int nf = 0; nf < 4; nf++)
                    MMA_F16(acc[mf][nf], af[mf], bf[nf]);
        }
    };

    int ntiles = Kpad >> 5;
    issue(0, 0);
    asm volatile("cp.async.commit_group;" ::: "memory");
    for (int it = 0; it < ntiles; it++) {
        if (it + 1 < ntiles) issue(it + 1, (it + 1) & 1);
        asm volatile("cp.async.commit_group;" ::: "memory");
        asm volatile("cp.async.wait_group 1;" ::: "memory");
        __syncthreads();
        compute(it & 1);
        __syncthreads();
    }

    // ---- epilogue ----
    float*  Cf = (float*) Cv;
    __half* Ch = (__half*)Cv;
    long long cbase = b*cOut + ii*cIn;
    #pragma unroll
    for (int mf = 0; mf < 4; mf++) {
        #pragma unroll
        for (int nf = 0; nf < 4; nf++) {
            int gn0 = n0 + wn + nf*8 + 2*t4;
            #pragma unroll
            for (int rr = 0; rr < 2; rr++) {
                int gm = m0 + wm + mf*16 + g + rr*8;
                if (gm >= Mr) continue;
                float v0 = acc[mf][nf][2*rr    ] * alpha;
                float v1 = acc[mf][nf][2*rr + 1] * alpha;
                if (bias) { v0 += bias[gn0]; v1 += bias[gn0 + 1]; }
                if (EPI == 1) { v0 = geluf(v0); v1 = geluf(v1); }
                long long off = cbase + (long long)gm*ldc + gn0;
                if (OUTH) {
                    if (gn0 + 1 < Nc)
                        *(__half2*)(Ch + off) = __floats2half2_rn(v0, v1);
                    else if (gn0 < Nc)
                        Ch[off] = __float2half_rn(v0);
                } else {
                    if (gn0 < Nc)     { if (ACCUM) Cf[off]   += v0; else Cf[off]   = v0; }
                    if (gn0 + 1 < Nc) { if (ACCUM) Cf[off+1] += v1; else Cf[off+1] = v1; }
                }
            }
        }
    }
}

// ---------------- output ---------------------------------------------------------
__global__ void out_k(const float* __restrict__ img, float* __restrict__ out) {
    int b = blockIdx.y, t = blockIdx.x;
    const float* src = (g_M[b] == 0)
        ? img + ((size_t)b*1024 + t) * 1024
        : g_X + ((size_t)b*NPAD + t) * 1024;
    float* o = out + ((size_t)b*1024 + t) * 1024;
    for (int c = threadIdx.x; c < 1024; c += 256) o[c] = src[c];
}

// ================================ host ==========================================
extern "C" void kernel_launch(void* const* d_in, const int* in_sizes, int n_in,
                              void* d_out, int out_size) {
    const float* img   = (const float*)d_in[0];
    const float* depth = (const float*)d_in[1];
    const int*   mask  = (const int*)  d_in[2];
    const float* gauss = (const float*)d_in[5];
    const float* w1    = (const float*)d_in[6];
    const float* b1    = (const float*)d_in[7];
    const float* w2    = (const float*)d_in[8];
    const float* b2    = (const float*)d_in[9];
    const float* sep   = (const float*)d_in[10];
    const float* ln1w  = (const float*)d_in[11];
    const float* ln1b  = (const float*)d_in[12];
    const float* qkvw  = (const float*)d_in[13];
    const float* qkvb  = (const float*)d_in[14];
    const float* projw = (const float*)d_in[15];
    const float* projb = (const float*)d_in[16];
    const float* ln2w  = (const float*)d_in[17];
    const float* ln2b  = (const float*)d_in[18];
    const float* m1w   = (const float*)d_in[19];
    const float* m1b   = (const float*)d_in[20];
    const float* m2w   = (const float*)d_in[21];
    const float* m2b   = (const float*)d_in[22];
    float* out = (float*)d_out;

    float *pX, *pS, *pQpe_, *pPft;
    __half *pYh, *pQKVh, *pSh, *pHh, *pVt, *pHph, *pWch;
    cudaGetSymbolAddress((void**)&pX,    g_X);
    cudaGetSymbolAddress((void**)&pS,    g_S);
    cudaGetSymbolAddress((void**)&pPft,  g_Pft);
    cudaGetSymbolAddress((void**)&pQpe_, g_Qpe);
    cudaGetSymbolAddress((void**)&pYh,   g_Yh);
    cudaGetSymbolAddress((void**)&pQKVh, g_QKVh);
    cudaGetSymbolAddress((void**)&pSh,   g_Sh);
    cudaGetSymbolAddress((void**)&pHh,   g_Hh);
    cudaGetSymbolAddress((void**)&pVt,   g_Vt);
    cudaGetSymbolAddress((void**)&pHph,  g_Hph);
    cudaGetSymbolAddress((void**)&pWch,  g_Wch);

    const long long SX   = (long long)NPAD * 1024;
    const long long SQKV = (long long)NPAD * 3072;
    const long long SH   = (long long)NPAD * 4096;
    const long long SS1  = (long long)NPAD * SLD;    // per head
    const long long SSB  = 4LL * SS1;                // per batch

    // --- transpose+round all GEMM weights to half [N][K] once per call ---
    {
        dim3 blk(32, 8);
        wtr_k<<<dim3(96, 32, 2),  blk>>>(qkvw,  pWch + WOFF_QKV,  1024, 3072);
        wtr_k<<<dim3(32, 32, 2),  blk>>>(projw, pWch + WOFF_PROJ, 1024, 1024);
        wtr_k<<<dim3(128, 32, 2), blk>>>(m1w,   pWch + WOFF_M1,   1024, 4096);
        wtr_k<<<dim3(32, 128, 2), blk>>>(m2w,   pWch + WOFF_M2,   4096, 1024);
        wtr_k<<<dim3(32, 16, 1),  blk>>>(w2,    pWch + WOFF_W2,    512, 1024);
    }
    const __half* qkvT  = pWch + WOFF_QKV;
    const __half* projT = pWch + WOFF_PROJ;
    const __half* m1T   = pWch + WOFF_M1;
    const __half* m2T   = pWch + WOFF_M2;
    const __half* w2T   = pWch + WOFF_W2;

    compact_k<<<1, NBATCH>>>(mask);
    qpe_k<<<1024, 256>>>(gauss);
    pembed_k<<<dim3(GPTS, NBATCH), 256>>>(depth, gauss, w1, b1);

    // prompt features: Pft = Hp @ w2 + b2 (rows = g_M[b]) -> fp32 (feeds X)
    gemm_h<0,false,false><<<dim3(8, 18, NBATCH), 256>>>(
        pHph, (long long)GPTS*512, 0, 512,
        w2T, 0, 0, 512,
        pPft, (long long)GPTS*1024, 0, 1024,
        b2, 1, 0, 1024, 512, 2, 0, 0, 1.0f);

    build_x<<<dim3(NMAXT, NBATCH), 256>>>(img, sep);

    for (int i = 0; i < 2; i++) {
        if (i) sep_rep<<<NBATCH, 256>>>(sep + (size_t)i*1024);

        ln_k<<<dim3(NMAXT, NBATCH), 256>>>(pX, pYh, ln1w + i*1024, ln1b + i*1024);

        // QKV = Y @ qkv_w + qkv_b  -> half
        gemm_h<0,false,true><<<dim3(24, 27, NBATCH), 256>>>(
            pYh, SX, 0, 1024,
            qkvT + (size_t)i*3072*1024, 0, 0, 1024,
            pQKVh, SQKV, 0, 3072,
            qkvb + (size_t)i*3072, 1, 0, 3072, 1024, 1, 0, 0, 1.0f);

        // V transpose for S@V B-operand
        vtr_k<<<dim3(105, 32, NBATCH), dim3(32, 8)>>>(pQKVh, pVt);

        // S = Q K^T / 16 -> fp32 logits (per head, z = b*4+h)
        gemm_h<0,false,false><<<dim3(27, 27, NBATCH*4), 256>>>(
            pQKVh, SQKV, 256, 3072,
            pQKVh + 1024, SQKV, 256, 3072,
            pS, SSB, SS1, SLD,
            nullptr, 4, 0, 0, 256, 1, 1, 0, 0.0625f);

        softmax_k<<<dim3(NMAXT, NBATCH*4), 256>>>();

        // O = Sh @ Vt^T -> Yh half (per-head column slice)
        gemm_h<0,false,true><<<dim3(2, 27, NBATCH*4), 256>>>(
            pSh, SSB, SS1, SLD,
            pVt, (long long)1024*NPAD, (long long)256*NPAD, NPAD,
            pYh, SX, 256, 1024,
            nullptr, 4, 0, 256, 0, 1, 0, 1, 1.0f);

        // X += O @ proj_w + proj_b  (residual fp32)
        gemm_h<0,true,false><<<dim3(8, 27, NBATCH), 256>>>(
            pYh, SX, 0, 1024,
            projT + (size_t)i*1024*1024, 0, 0, 1024,
            pX, SX, 0, 1024,
            projb + (size_t)i*1024, 1, 0, 1024, 1024, 1, 0, 0, 1.0f);

        ln_k<<<dim3(NMAXT, NBATCH), 256>>>(pX, pYh, ln2w + i*1024, ln2b + i*1024);

        // H = gelu(Y @ mlp_w1 + mlp_b1) -> half
        gemm_h<1,false,true><<<dim3(32, 27, NBATCH), 256>>>(
            pYh, SX, 0, 1024,
            m1T + (size_t)i*4096*1024, 0, 0, 1024,
            pHh, SH, 0, 4096,
            m1b + (size_t)i*4096, 1, 0, 4096, 1024, 1, 0, 0, 1.0f);

        // X += H @ mlp_w2 + mlp_b2  (residual fp32)
        gemm_h<0,true,false><<<dim3(8, 27, NBATCH), 256>>>(
            pHh, SH, 0, 4096,
            m2T + (size_t)i*1024*4096, 0, 0, 4096,
            pX, SX, 0, 1024,
            m2b + (size_t)i*1024, 1, 0, 1024, 4096, 1, 0, 0, 1.0f);
    }

    out_k<<<dim3(1024, NBATCH), 256>>>(img, out);
}